// round 15
// baseline (speedup 1.0000x reference)
#include <cuda_runtime.h>
#include <cuda_fp16.h>
#include <mma.h>
#include <cstdint>
#include <cstddef>

using namespace nvcuda;

// B=4, S=2048, D=DK=DV=1024. Scratch: __device__ globals only.
__device__ __half g_Xh  [(size_t)8192 * 1024];         // fp16 X
__device__ __half g_Wh  [(size_t)3 * 1024 * 1024];     // fp16 Wq|Wk|Wv contiguous
__device__ __half g_QKV [(size_t)3 * 8192 * 1024];     // fp16 Q|K|V contiguous
__device__ __half g_P   [(size_t)4 * 2048 * 2048];     // exp(logit-4) fp16
__device__ float  g_Rp  [(size_t)8192 * 32];           // per-row partial sums

__device__ __forceinline__ void cp16(uint32_t dst, const void* src) {
    asm volatile("cp.async.cg.shared.global [%0], [%1], 16;"
                 :: "r"(dst), "l"(src) : "memory");
}
__device__ __forceinline__ uint32_t smem_u32(const void* p) {
    uint32_t a;
    asm("{ .reg .u64 t; cvta.to.shared.u64 t, %1; cvt.u32.u64 %0, t; }"
        : "=r"(a) : "l"(p));
    return a;
}

// ---------------------------------------------------------------------------
// fp16 wmma GEMM, 128x128 CTA tile, BK=64, 3-stage cp.async pipeline.
// 4 warps (128 threads), warp tile 64x64 (2x2 warp grid). Mainloop identical
// to the R11/R14 kernel (measured 415.7us); MODE work stays OUT of mainloop.
// BT=1: B is [N,K] row-major (C = A @ B^T); BT=0: B is [K,N] row-major.
// MODE 0: fused QKV projection (grid.x=24, w=x>>3): out = half(v + bias[col])
// MODE 1: out = half(exp(v*scale - 4)); epilogue also writes per-row partial
//         sums of the exps to Rpart[row*32 + bx*2 + (wid&1)]
// MODE 2: out = float(v * rinv[row]); PROLOGUE folds this CTA's 128 rows'
//         32 partials from Rpart into a smem rinv table (reads overlap the
//         cp.async pipeline fill; ordered before use by mainloop barriers).
// Row strides: A/B-trans 72 halves (144 B ≡ 16 mod 128 -> conflict-free),
// B non-trans 136 halves (272 B ≡ 16 mod 128).
// ---------------------------------------------------------------------------
constexpr int LDA   = 72;
constexpr int LDBN  = 136;
constexpr int STAGE = 36864;
constexpr int SMEM_TOTAL = 3 * STAGE + 512;  // +512: MODE2 rinv table; 2 CTAs/SM

template <int BT, int MODE>
__global__ void __launch_bounds__(128, 2) gemm_h(
    const __half* __restrict__ A, const __half* __restrict__ Bm,
    const float* __restrict__ bq, const float* __restrict__ bk,
    const float* __restrict__ bv, float* __restrict__ Rpart,
    void* __restrict__ Cv,
    int N_, int K, size_t strA, size_t strB, size_t strC, float scale)
{
    extern __shared__ char smem[];
    const uint32_t sbase = smem_u32(smem);
    const int tid = threadIdx.x, wid = tid >> 5, lane = tid & 31;

    const float* bias = nullptr;
    int n0;
    if (MODE == 0) {
        const int w = blockIdx.x >> 3;
        n0 = (blockIdx.x & 7) * 128;
        Bm += (size_t)w * 1048576;                    // w-th weight matrix
        Cv = (void*)((__half*)Cv + (size_t)w * 8388608);
        bias = (w == 0) ? bq : (w == 1) ? bk : bv;
    } else {
        n0 = blockIdx.x * 128;
        A  += (size_t)blockIdx.z * strA;
        Bm += (size_t)blockIdx.z * strB;
    }
    const int m0 = blockIdx.y * 128;
    const int mw = (wid >> 1) * 64;   // warp row offset (2x2 warp grid)
    const int nw = (wid & 1) * 64;    // warp col offset
    const int nch = K >> 6;

    wmma::fragment<wmma::accumulator, 16, 16, 16, float> acc[4][4];
#pragma unroll
    for (int i = 0; i < 4; i++)
#pragma unroll
        for (int j = 0; j < 4; j++) wmma::fill_fragment(acc[i][j], 0.0f);

    auto load_chunk = [&](int c, int s) {
        const uint32_t sA = sbase + (uint32_t)s * STAGE;
        const uint32_t sB = sA + 18432u;
#pragma unroll
        for (int i = 0; i < 8; i++) {                 // A: 128 rows x 64 halves
            int lin = tid + i * 128;
            int r = lin >> 3, c8 = (lin & 7) * 8;
            cp16(sA + (uint32_t)(r * 144 + c8 * 2),
                 A + (size_t)(m0 + r) * K + c * 64 + c8);
        }
        if (BT) {                                     // B: 128 rows x 64 halves
#pragma unroll
            for (int i = 0; i < 8; i++) {
                int lin = tid + i * 128;
                int r = lin >> 3, c8 = (lin & 7) * 8;
                cp16(sB + (uint32_t)(r * 144 + c8 * 2),
                     Bm + (size_t)(n0 + r) * K + c * 64 + c8);
            }
        } else {                                      // B: 64 rows x 128 halves
#pragma unroll
            for (int i = 0; i < 8; i++) {
                int lin = tid + i * 128;
                int r = lin >> 4, c8 = (lin & 15) * 8;
                cp16(sB + (uint32_t)(r * 272 + c8 * 2),
                     Bm + (size_t)(c * 64 + r) * N_ + n0 + c8);
            }
        }
    };

    auto compute = [&](int s) {
        const __half* hA = reinterpret_cast<const __half*>(smem + (size_t)s * STAGE);
        const __half* hB = reinterpret_cast<const __half*>(smem + (size_t)s * STAGE + 18432);
#pragma unroll
        for (int ko = 0; ko < 4; ko++) {
            wmma::fragment<wmma::matrix_a, 16, 16, 16, __half, wmma::row_major> af[4];
#pragma unroll
            for (int i = 0; i < 4; i++)
                wmma::load_matrix_sync(af[i], hA + (mw + i * 16) * LDA + ko * 16, LDA);
#pragma unroll
            for (int j = 0; j < 4; j++) {
                if (BT) {
                    wmma::fragment<wmma::matrix_b, 16, 16, 16, __half, wmma::col_major> bf;
                    wmma::load_matrix_sync(bf, hB + (nw + j * 16) * LDA + ko * 16, LDA);
#pragma unroll
                    for (int i = 0; i < 4; i++)
                        wmma::mma_sync(acc[i][j], af[i], bf, acc[i][j]);
                } else {
                    wmma::fragment<wmma::matrix_b, 16, 16, 16, __half, wmma::row_major> bf;
                    wmma::load_matrix_sync(bf, hB + (ko * 16) * LDBN + nw + j * 16, LDBN);
#pragma unroll
                    for (int i = 0; i < 4; i++)
                        wmma::mma_sync(acc[i][j], af[i], bf, acc[i][j]);
                }
            }
        }
    };

    load_chunk(0, 0);
    asm volatile("cp.async.commit_group;" ::: "memory");
    load_chunk(1, 1);
    asm volatile("cp.async.commit_group;" ::: "memory");

    if (MODE == 2) {
        // Fold this CTA's 128 row-sums (32 fp32 partials each) -> smem 1/sum.
        // Same summation order as the old rowinv32 kernel (bit-identical).
        // Global reads overlap the cp.async pipeline fill; the mainloop's
        // first __syncthreads orders the smem writes before any epilogue read.
        const float4* p = reinterpret_cast<const float4*>(
            Rpart + ((size_t)blockIdx.z * 2048 + m0 + tid) * 32);
        float s = 0.0f;
#pragma unroll
        for (int q = 0; q < 8; q++) {
            float4 v = p[q];
            s += (v.x + v.y) + (v.z + v.w);
        }
        reinterpret_cast<float*>(smem + 3 * STAGE)[tid] = 1.0f / s;
    }

    for (int c = 0; c < nch; c++) {
        asm volatile("cp.async.wait_group 1;" ::: "memory");
        __syncthreads();
        if (c + 2 < nch) load_chunk(c + 2, (c + 2) % 3);
        asm volatile("cp.async.commit_group;" ::: "memory");
        compute(c % 3);
    }
    __syncthreads();

    // Epilogue: per-warp 16x16 staging, vectorized 4-wide stores.
    float* stg = reinterpret_cast<float*>(smem) + wid * 16 * 20;
    const float* rinv_s = reinterpret_cast<const float*>(smem + 3 * STAGE);
    float rs[4][2];                      // MODE1: per-thread row partials
    if (MODE == 1) {
#pragma unroll
        for (int i = 0; i < 4; i++) { rs[i][0] = 0.0f; rs[i][1] = 0.0f; }
    }
#pragma unroll
    for (int i = 0; i < 4; i++) {
#pragma unroll
        for (int j = 0; j < 4; j++) {
            wmma::store_matrix_sync(stg, acc[i][j], 20, wmma::mem_row_major);
            __syncwarp();
#pragma unroll
            for (int l = 0; l < 2; l++) {
                const int item = lane + l * 32;
                const int r = item >> 2, g = item & 3;
                const int row = m0 + mw + i * 16 + r;
                const int col = n0 + nw + j * 16 + g * 4;
                const size_t idx = (size_t)blockIdx.z * strC + (size_t)row * N_ + col;
                float4 v = *reinterpret_cast<const float4*>(&stg[r * 20 + g * 4]);
                if (MODE == 0) {
                    const float4 b4 = *reinterpret_cast<const float4*>(&bias[col]);
                    __half2 h0 = __floats2half2_rn(v.x + b4.x, v.y + b4.y);
                    __half2 h1 = __floats2half2_rn(v.z + b4.z, v.w + b4.w);
                    uint2 u = {*reinterpret_cast<uint32_t*>(&h0),
                               *reinterpret_cast<uint32_t*>(&h1)};
                    *reinterpret_cast<uint2*>((__half*)Cv + idx) = u;
                } else if (MODE == 1) {
                    const float e0 = __expf(v.x * scale - 4.0f);
                    const float e1 = __expf(v.y * scale - 4.0f);
                    const float e2 = __expf(v.z * scale - 4.0f);
                    const float e3 = __expf(v.w * scale - 4.0f);
                    rs[i][l] += (e0 + e1) + (e2 + e3);
                    __half2 h0 = __floats2half2_rn(e0, e1);
                    __half2 h1 = __floats2half2_rn(e2, e3);
                    uint2 u = {*reinterpret_cast<uint32_t*>(&h0),
                               *reinterpret_cast<uint32_t*>(&h1)};
                    *reinterpret_cast<uint2*>((__half*)Cv + idx) = u;
                } else {
                    const float rv = rinv_s[mw + i * 16 + r];
                    v.x *= rv; v.y *= rv; v.z *= rv; v.w *= rv;
                    *reinterpret_cast<float4*>((float*)Cv + idx) = v;
                }
            }
            __syncwarp();
        }
    }
    if (MODE == 1) {
        // Reduce across the 4 lanes sharing a row (lane&3 = col group),
        // then lane&3==0 writes this warp's 64-col partial for its row.
#pragma unroll
        for (int i = 0; i < 4; i++)
#pragma unroll
            for (int l = 0; l < 2; l++) {
                float s = rs[i][l];
                s += __shfl_xor_sync(0xffffffffu, s, 1);
                s += __shfl_xor_sync(0xffffffffu, s, 2);
                if ((lane & 3) == 0) {
                    const int row = m0 + mw + i * 16 + 8 * l + (lane >> 2);
                    Rpart[((size_t)blockIdx.z * 2048 + row) * 32 +
                          blockIdx.x * 2 + (wid & 1)] = s;
                }
            }
    }
}

// ---------------------------------------------------------------------------
// fp32 -> fp16 conversion. grid.y selects among up to 3 source matrices.
// ---------------------------------------------------------------------------
__global__ void __launch_bounds__(256) f2h3(const float* __restrict__ s0,
                                            const float* __restrict__ s1,
                                            const float* __restrict__ s2,
                                            __half* __restrict__ out,
                                            int n4_per)
{
    const int z = blockIdx.y;
    const float* in = (z == 0) ? s0 : (z == 1) ? s1 : s2;
    __half* dst = out + (size_t)z * n4_per * 4;
    int i = blockIdx.x * blockDim.x + threadIdx.x;
    if (i < n4_per) {
        float4 v = reinterpret_cast<const float4*>(in)[i];
        __half2 h0 = __floats2half2_rn(v.x, v.y);
        __half2 h1 = __floats2half2_rn(v.z, v.w);
        uint2 u;
        u.x = *reinterpret_cast<uint32_t*>(&h0);
        u.y = *reinterpret_cast<uint32_t*>(&h1);
        reinterpret_cast<uint2*>(dst)[i] = u;
    }
}

// ---------------------------------------------------------------------------
// kernel_launch
// ---------------------------------------------------------------------------
extern "C" void kernel_launch(void* const* d_in, const int* in_sizes, int n_in,
                              void* d_out, int out_size)
{
    (void)in_sizes; (void)n_in; (void)out_size;
    const float* X  = (const float*)d_in[0];
    const float* Wq = (const float*)d_in[1];
    const float* Wk = (const float*)d_in[2];
    const float* Wv = (const float*)d_in[3];
    const float* bq = (const float*)d_in[4];
    const float* bk = (const float*)d_in[5];
    const float* bv = (const float*)d_in[6];
    float* O = (float*)d_out;

    __half *Xh, *Wh, *QKV, *P;
    float *Rp;
    cudaGetSymbolAddress((void**)&Xh,  g_Xh);
    cudaGetSymbolAddress((void**)&Wh,  g_Wh);
    cudaGetSymbolAddress((void**)&QKV, g_QKV);
    cudaGetSymbolAddress((void**)&P,   g_P);
    cudaGetSymbolAddress((void**)&Rp,  g_Rp);

    cudaFuncSetAttribute(gemm_h<0, 0>, cudaFuncAttributeMaxDynamicSharedMemorySize, SMEM_TOTAL);
    cudaFuncSetAttribute(gemm_h<1, 1>, cudaFuncAttributeMaxDynamicSharedMemorySize, SMEM_TOTAL);
    cudaFuncSetAttribute(gemm_h<0, 2>, cudaFuncAttributeMaxDynamicSharedMemorySize, SMEM_TOTAL);

    const size_t sQK = (size_t)2048 * 1024;
    const size_t sSS = (size_t)2048 * 2048;

    __half* Qh = QKV;
    __half* Kh = QKV + (size_t)8192 * 1024;
    __half* Vh = QKV + (size_t)2 * 8192 * 1024;

    // fp16 operand streams: X (one launch) + all 3 weights (one launch)
    f2h3<<<dim3(8192, 1), 256>>>(X, X, X, Xh, 8192 * 1024 / 4);
    f2h3<<<dim3(1024, 3), 256>>>(Wq, Wk, Wv, Wh, 1024 * 1024 / 4);

    // Fused projections: one launch computes Q, K, V (+bias), fp16
    dim3 gproj(24, 64, 1);
    gemm_h<0, 0><<<gproj, 128, SMEM_TOTAL>>>(Xh, Wh, bq, bk, bv, nullptr, QKV,
                                             1024, 1024, 0, 0, 0, 1.0f);

    // Logits -> unnormalized probs + per-row partial sums (epilogue-harvested)
    dim3 glog(16, 16, 4);
    gemm_h<1, 1><<<glog, 128, SMEM_TOTAL>>>(Qh, Kh, nullptr, nullptr, nullptr,
                                            Rp, P, 2048, 1024,
                                            sQK, sQK, sSS, 0.03125f);

    // Output: O[b] = (P[b] @ V[b]) * rinv; rinv folded in-kernel from Rpart
    dim3 gout(8, 16, 4);
    gemm_h<0, 2><<<gout, 128, SMEM_TOTAL>>>(P, Vh, nullptr, nullptr, nullptr,
                                            Rp, O, 1024, 2048,
                                            sSS, sQK, sQK, 1.0f);
}

// round 16
// speedup vs baseline: 1.0182x; 1.0182x over previous
#include <cuda_runtime.h>
#include <cuda_fp16.h>
#include <mma.h>
#include <cstdint>
#include <cstddef>

using namespace nvcuda;

// B=4, S=2048, D=DK=DV=1024. Scratch: __device__ globals only.
__device__ __half g_Xh  [(size_t)8192 * 1024];         // fp16 X
__device__ __half g_Wh  [(size_t)3 * 1024 * 1024];     // fp16 Wq|Wk|Wv contiguous
__device__ __half g_QKV [(size_t)3 * 8192 * 1024];     // fp16 Q|K|V contiguous
__device__ __half g_P   [(size_t)4 * 2048 * 2048];     // exp(logit-4) fp16
__device__ float  g_Rp  [(size_t)8192 * 32];           // per-row partial sums
__device__ float  g_R   [8192];                        // per-row 1/sum

__device__ __forceinline__ void cp16(uint32_t dst, const void* src) {
    asm volatile("cp.async.cg.shared.global [%0], [%1], 16;"
                 :: "r"(dst), "l"(src) : "memory");
}
__device__ __forceinline__ uint32_t smem_u32(const void* p) {
    uint32_t a;
    asm("{ .reg .u64 t; cvta.to.shared.u64 t, %1; cvt.u32.u64 %0, t; }"
        : "=r"(a) : "l"(p));
    return a;
}

// ---------------------------------------------------------------------------
// fp16 wmma GEMM, 128x128 CTA tile, BK=64, 3-stage cp.async pipeline.
// 4 warps (128 threads), warp tile 64x64 (2x2 warp grid). Mainloop identical
// to the R11/R14 kernel (measured 415.7us).
// EPILOGUE: direct accumulator-fragment stores (no smem staging). HMMA.16816
// fp32 acc layout: lane holds rows r0=lane>>2, r1=r0+8; cols c0=(lane&3)*2,
// c0+8; fragment regs x[0,1]=(r0,c0..), x[2,3]=(r1,c0..), x[4,5]=(r0,c0+8..),
// x[6,7]=(r1,c0+8..).
// BT=1: B is [N,K] row-major (C = A @ B^T); BT=0: B is [K,N] row-major.
// MODE 0: fused QKV projection (grid.x=24, w=x>>3): out = half(v + bias[col])
// MODE 1: out = half(exp(v*scale - 4)); also per-row partial sums -> Rpart
// MODE 2: out = float(v * rowinv[row])   (AV, normalized)
// Row strides: A/B-trans 72 halves (144 B ≡ 16 mod 128 -> conflict-free),
// B non-trans 136 halves (272 B ≡ 16 mod 128).
// ---------------------------------------------------------------------------
constexpr int LDA   = 72;
constexpr int LDBN  = 136;
constexpr int STAGE = 36864;
constexpr int SMEM_TOTAL = 3 * STAGE;  // 110592 -> 2 CTAs/SM

template <int BT, int MODE>
__global__ void __launch_bounds__(128, 2) gemm_h(
    const __half* __restrict__ A, const __half* __restrict__ Bm,
    const float* __restrict__ bq, const float* __restrict__ bk,
    const float* __restrict__ bv, const float* __restrict__ rowinv,
    float* __restrict__ Rpart, void* __restrict__ Cv,
    int N_, int K, size_t strA, size_t strB, size_t strC, float scale)
{
    extern __shared__ char smem[];
    const uint32_t sbase = smem_u32(smem);
    const int tid = threadIdx.x, wid = tid >> 5, lane = tid & 31;

    const float* bias = nullptr;
    int n0;
    if (MODE == 0) {
        const int w = blockIdx.x >> 3;
        n0 = (blockIdx.x & 7) * 128;
        Bm += (size_t)w * 1048576;                    // w-th weight matrix
        Cv = (void*)((__half*)Cv + (size_t)w * 8388608);
        bias = (w == 0) ? bq : (w == 1) ? bk : bv;
    } else {
        n0 = blockIdx.x * 128;
        A  += (size_t)blockIdx.z * strA;
        Bm += (size_t)blockIdx.z * strB;
    }
    const int m0 = blockIdx.y * 128;
    const int mw = (wid >> 1) * 64;   // warp row offset (2x2 warp grid)
    const int nw = (wid & 1) * 64;    // warp col offset
    const int nch = K >> 6;

    wmma::fragment<wmma::accumulator, 16, 16, 16, float> acc[4][4];
#pragma unroll
    for (int i = 0; i < 4; i++)
#pragma unroll
        for (int j = 0; j < 4; j++) wmma::fill_fragment(acc[i][j], 0.0f);

    auto load_chunk = [&](int c, int s) {
        const uint32_t sA = sbase + (uint32_t)s * STAGE;
        const uint32_t sB = sA + 18432u;
#pragma unroll
        for (int i = 0; i < 8; i++) {                 // A: 128 rows x 64 halves
            int lin = tid + i * 128;
            int r = lin >> 3, c8 = (lin & 7) * 8;
            cp16(sA + (uint32_t)(r * 144 + c8 * 2),
                 A + (size_t)(m0 + r) * K + c * 64 + c8);
        }
        if (BT) {                                     // B: 128 rows x 64 halves
#pragma unroll
            for (int i = 0; i < 8; i++) {
                int lin = tid + i * 128;
                int r = lin >> 3, c8 = (lin & 7) * 8;
                cp16(sB + (uint32_t)(r * 144 + c8 * 2),
                     Bm + (size_t)(n0 + r) * K + c * 64 + c8);
            }
        } else {                                      // B: 64 rows x 128 halves
#pragma unroll
            for (int i = 0; i < 8; i++) {
                int lin = tid + i * 128;
                int r = lin >> 4, c8 = (lin & 15) * 8;
                cp16(sB + (uint32_t)(r * 272 + c8 * 2),
                     Bm + (size_t)(c * 64 + r) * N_ + n0 + c8);
            }
        }
    };

    auto compute = [&](int s) {
        const __half* hA = reinterpret_cast<const __half*>(smem + (size_t)s * STAGE);
        const __half* hB = reinterpret_cast<const __half*>(smem + (size_t)s * STAGE + 18432);
#pragma unroll
        for (int ko = 0; ko < 4; ko++) {
            wmma::fragment<wmma::matrix_a, 16, 16, 16, __half, wmma::row_major> af[4];
#pragma unroll
            for (int i = 0; i < 4; i++)
                wmma::load_matrix_sync(af[i], hA + (mw + i * 16) * LDA + ko * 16, LDA);
#pragma unroll
            for (int j = 0; j < 4; j++) {
                if (BT) {
                    wmma::fragment<wmma::matrix_b, 16, 16, 16, __half, wmma::col_major> bf;
                    wmma::load_matrix_sync(bf, hB + (nw + j * 16) * LDA + ko * 16, LDA);
#pragma unroll
                    for (int i = 0; i < 4; i++)
                        wmma::mma_sync(acc[i][j], af[i], bf, acc[i][j]);
                } else {
                    wmma::fragment<wmma::matrix_b, 16, 16, 16, __half, wmma::row_major> bf;
                    wmma::load_matrix_sync(bf, hB + (ko * 16) * LDBN + nw + j * 16, LDBN);
#pragma unroll
                    for (int i = 0; i < 4; i++)
                        wmma::mma_sync(acc[i][j], af[i], bf, acc[i][j]);
                }
            }
        }
    };

    load_chunk(0, 0);
    asm volatile("cp.async.commit_group;" ::: "memory");
    load_chunk(1, 1);
    asm volatile("cp.async.commit_group;" ::: "memory");

    for (int c = 0; c < nch; c++) {
        asm volatile("cp.async.wait_group 1;" ::: "memory");
        __syncthreads();
        if (c + 2 < nch) load_chunk(c + 2, (c + 2) % 3);
        asm volatile("cp.async.commit_group;" ::: "memory");
        compute(c % 3);
    }
    __syncthreads();

    // ---- Direct epilogue: store straight from accumulator fragments. ----
    const int r0 = lane >> 2;           // row within 16-row tile (and r0+8)
    const int cb = (lane & 3) * 2;      // col pair base (and cb+8)
    float rs[4][2];                     // MODE1 partials: [i][0]=r0 rows, [1]=r1
    if (MODE == 1) {
#pragma unroll
        for (int i = 0; i < 4; i++) { rs[i][0] = 0.0f; rs[i][1] = 0.0f; }
    }
#pragma unroll
    for (int i = 0; i < 4; i++) {
        const int rowA = m0 + mw + i * 16 + r0;
        const int rowB = rowA + 8;
        float rvA, rvB;
        if (MODE == 2) {
            rvA = rowinv[blockIdx.z * 2048 + rowA];
            rvB = rowinv[blockIdx.z * 2048 + rowB];
        }
#pragma unroll
        for (int j = 0; j < 4; j++) {
            const float* x = acc[i][j].x;
            const int c0 = n0 + nw + j * 16 + cb;      // pairs at c0, c0+8
#pragma unroll
            for (int h = 0; h < 2; h++) {              // h: col-half (+8*h)
                const int col = c0 + 8 * h;
                const float v0 = x[4 * h + 0], v1 = x[4 * h + 1];  // row r0
                const float w0 = x[4 * h + 2], w1 = x[4 * h + 3];  // row r1
                const size_t iA = (size_t)blockIdx.z * strC + (size_t)rowA * N_ + col;
                const size_t iB = (size_t)blockIdx.z * strC + (size_t)rowB * N_ + col;
                if (MODE == 0) {
                    const float2 b2 = *reinterpret_cast<const float2*>(&bias[col]);
                    __half2 hA2 = __floats2half2_rn(v0 + b2.x, v1 + b2.y);
                    __half2 hB2 = __floats2half2_rn(w0 + b2.x, w1 + b2.y);
                    *reinterpret_cast<uint32_t*>((__half*)Cv + iA) =
                        *reinterpret_cast<uint32_t*>(&hA2);
                    *reinterpret_cast<uint32_t*>((__half*)Cv + iB) =
                        *reinterpret_cast<uint32_t*>(&hB2);
                } else if (MODE == 1) {
                    const float e0 = __expf(v0 * scale - 4.0f);
                    const float e1 = __expf(v1 * scale - 4.0f);
                    const float f0 = __expf(w0 * scale - 4.0f);
                    const float f1 = __expf(w1 * scale - 4.0f);
                    rs[i][0] += e0 + e1;
                    rs[i][1] += f0 + f1;
                    __half2 hA2 = __floats2half2_rn(e0, e1);
                    __half2 hB2 = __floats2half2_rn(f0, f1);
                    *reinterpret_cast<uint32_t*>((__half*)Cv + iA) =
                        *reinterpret_cast<uint32_t*>(&hA2);
                    *reinterpret_cast<uint32_t*>((__half*)Cv + iB) =
                        *reinterpret_cast<uint32_t*>(&hB2);
                } else {
                    float2 pA = {v0 * rvA, v1 * rvA};
                    float2 pB = {w0 * rvB, w1 * rvB};
                    *reinterpret_cast<float2*>((float*)Cv + iA) = pA;
                    *reinterpret_cast<float2*>((float*)Cv + iB) = pB;
                }
            }
        }
    }
    if (MODE == 1) {
        // Reduce across the 4 lanes sharing a row (lane&3 varies), then
        // lane&3==0 writes this warp's 64-col partials for rows r0, r0+8.
#pragma unroll
        for (int i = 0; i < 4; i++)
#pragma unroll
            for (int l = 0; l < 2; l++) {
                float s = rs[i][l];
                s += __shfl_xor_sync(0xffffffffu, s, 1);
                s += __shfl_xor_sync(0xffffffffu, s, 2);
                if ((lane & 3) == 0) {
                    const int row = m0 + mw + i * 16 + 8 * l + r0;
                    Rpart[((size_t)blockIdx.z * 2048 + row) * 32 +
                          blockIdx.x * 2 + (wid & 1)] = s;
                }
            }
    }
}

// ---------------------------------------------------------------------------
// fp32 -> fp16 conversion. grid.y selects among up to 3 source matrices.
// ---------------------------------------------------------------------------
__global__ void __launch_bounds__(256) f2h3(const float* __restrict__ s0,
                                            const float* __restrict__ s1,
                                            const float* __restrict__ s2,
                                            __half* __restrict__ out,
                                            int n4_per)
{
    const int z = blockIdx.y;
    const float* in = (z == 0) ? s0 : (z == 1) ? s1 : s2;
    __half* dst = out + (size_t)z * n4_per * 4;
    int i = blockIdx.x * blockDim.x + threadIdx.x;
    if (i < n4_per) {
        float4 v = reinterpret_cast<const float4*>(in)[i];
        __half2 h0 = __floats2half2_rn(v.x, v.y);
        __half2 h1 = __floats2half2_rn(v.z, v.w);
        uint2 u;
        u.x = *reinterpret_cast<uint32_t*>(&h0);
        u.y = *reinterpret_cast<uint32_t*>(&h1);
        reinterpret_cast<uint2*>(dst)[i] = u;
    }
}

// ---------------------------------------------------------------------------
// Fold 32 partials per row -> 1/sum. One thread per row.
// ---------------------------------------------------------------------------
__global__ void __launch_bounds__(256) rowinv32(const float* __restrict__ Rpart,
                                                float* __restrict__ R)
{
    const int row = blockIdx.x * blockDim.x + threadIdx.x;  // 0..8191
    const float4* p = reinterpret_cast<const float4*>(Rpart + (size_t)row * 32);
    float s = 0.0f;
#pragma unroll
    for (int q = 0; q < 8; q++) {
        float4 v = p[q];
        s += (v.x + v.y) + (v.z + v.w);
    }
    R[row] = 1.0f / s;
}

// ---------------------------------------------------------------------------
// kernel_launch
// ---------------------------------------------------------------------------
extern "C" void kernel_launch(void* const* d_in, const int* in_sizes, int n_in,
                              void* d_out, int out_size)
{
    (void)in_sizes; (void)n_in; (void)out_size;
    const float* X  = (const float*)d_in[0];
    const float* Wq = (const float*)d_in[1];
    const float* Wk = (const float*)d_in[2];
    const float* Wv = (const float*)d_in[3];
    const float* bq = (const float*)d_in[4];
    const float* bk = (const float*)d_in[5];
    const float* bv = (const float*)d_in[6];
    float* O = (float*)d_out;

    __half *Xh, *Wh, *QKV, *P;
    float *Rp, *R;
    cudaGetSymbolAddress((void**)&Xh,  g_Xh);
    cudaGetSymbolAddress((void**)&Wh,  g_Wh);
    cudaGetSymbolAddress((void**)&QKV, g_QKV);
    cudaGetSymbolAddress((void**)&P,   g_P);
    cudaGetSymbolAddress((void**)&Rp,  g_Rp);
    cudaGetSymbolAddress((void**)&R,   g_R);

    cudaFuncSetAttribute(gemm_h<0, 0>, cudaFuncAttributeMaxDynamicSharedMemorySize, SMEM_TOTAL);
    cudaFuncSetAttribute(gemm_h<1, 1>, cudaFuncAttributeMaxDynamicSharedMemorySize, SMEM_TOTAL);
    cudaFuncSetAttribute(gemm_h<0, 2>, cudaFuncAttributeMaxDynamicSharedMemorySize, SMEM_TOTAL);

    const size_t sQK = (size_t)2048 * 1024;
    const size_t sSS = (size_t)2048 * 2048;

    __half* Qh = QKV;
    __half* Kh = QKV + (size_t)8192 * 1024;
    __half* Vh = QKV + (size_t)2 * 8192 * 1024;

    // fp16 operand streams: X (one launch) + all 3 weights (one launch)
    f2h3<<<dim3(8192, 1), 256>>>(X, X, X, Xh, 8192 * 1024 / 4);
    f2h3<<<dim3(1024, 3), 256>>>(Wq, Wk, Wv, Wh, 1024 * 1024 / 4);

    // Fused projections: one launch computes Q, K, V (+bias), fp16
    dim3 gproj(24, 64, 1);
    gemm_h<0, 0><<<gproj, 128, SMEM_TOTAL>>>(Xh, Wh, bq, bk, bv, nullptr,
                                             nullptr, QKV,
                                             1024, 1024, 0, 0, 0, 1.0f);

    // Logits -> unnormalized probs + per-row partial sums (epilogue-harvested)
    dim3 glog(16, 16, 4);
    gemm_h<1, 1><<<glog, 128, SMEM_TOTAL>>>(Qh, Kh, nullptr, nullptr, nullptr,
                                            nullptr, Rp, P, 2048, 1024,
                                            sQK, sQK, sSS, 0.03125f);

    // Fold 32 partials/row -> 1/sum (1 MB read, ~2us)
    rowinv32<<<32, 256>>>(Rp, R);

    // Output: O[b] = (P[b] @ V[b]) * rowinv, fp32
    dim3 gout(8, 16, 4);
    gemm_h<0, 2><<<gout, 128, SMEM_TOTAL>>>(P, Vh, nullptr, nullptr, nullptr,
                                            R, nullptr, O, 1024, 2048,
                                            sSS, sQK, sQK, 1.0f);
}